// round 3
// baseline (speedup 1.0000x reference)
#include <cuda_runtime.h>
#include <cuda_bf16.h>

#define OUT_UNITS 128
#define MAX_ROWS  16384
#define WARPS_PER_BLOCK 8

// ---------------------------------------------------------------------------
// Scratch (device globals — no allocation allowed in kernel_launch)
// ---------------------------------------------------------------------------
__device__ int g_is64;                       // 1 if rows/cols are int64, 0 if int32
__device__ int g_row_start[MAX_ROWS + 1];    // CSR-style row offsets

// ---------------------------------------------------------------------------
// Dtype probe: rows sorted ascending over [0, 16384). If int64 (LE), every odd
// 32-bit word is a zero high-half. If int32, odd words near n/4, n/2, 3n/4 are
// sorted row ids ~4096/8192/12288. Probed indices odd and < n: safe for both.
// ---------------------------------------------------------------------------
__device__ __forceinline__ int probe_is64(const int* __restrict__ rows32, int n) {
    int j1 = (n / 2) | 1;
    int j2 = (n / 4) | 1;
    int j3 = (int)(((long long)3 * n) / 4) | 1;
    int s = rows32[j1] | rows32[j2] | rows32[j3];
    return (s == 0) ? 1 : 0;
}

// ---------------------------------------------------------------------------
// Kernel 1: build row offsets from sorted COO rows (fused dtype detection).
// 4 elements per thread, vectorized int4 loads.
// ---------------------------------------------------------------------------
__global__ void build_offsets_kernel(const int* __restrict__ rows32, int nnz, int n_rows) {
    const int is64 = probe_is64(rows32, nnz);

    const int t  = blockIdx.x * blockDim.x + threadIdx.x;
    if (t == 0) g_is64 = is64;
    const int k0 = t * 4;
    if (k0 >= nnz) return;

    const int cnt = min(4, nnz - k0);
    int r[4];
    if (is64) {
        if (cnt == 4) {
            // rows stored as int64: int4 covers 2 values (x=lo0, z=lo1)
            const int4 a = ((const int4*)rows32)[k0 / 2];
            const int4 b = ((const int4*)rows32)[k0 / 2 + 1];
            r[0] = a.x; r[1] = a.z; r[2] = b.x; r[3] = b.z;
        } else {
            for (int j = 0; j < cnt; j++) r[j] = rows32[2 * (k0 + j)];
        }
    } else {
        if (cnt == 4) {
            const int4 a = ((const int4*)rows32)[k0 / 4];
            r[0] = a.x; r[1] = a.y; r[2] = a.z; r[3] = a.w;
        } else {
            for (int j = 0; j < cnt; j++) r[j] = rows32[k0 + j];
        }
    }

    int rp = (k0 == 0) ? -1 : (is64 ? rows32[2 * (k0 - 1)] : rows32[k0 - 1]);
    for (int j = 0; j < cnt; j++) {
        const int rj = r[j];
        for (int x = rp + 1; x <= rj; x++) g_row_start[x] = k0 + j;
        rp = rj;
    }
    if (k0 + cnt == nnz) {
        for (int x = rp + 1; x <= n_rows; x++) g_row_start[x] = nnz;
    }
}

// ---------------------------------------------------------------------------
// Kernel 2: main SpMM. One WARP per output row; lane t owns output columns
// [4t, 4t+4) via float4. Stage 32 (val, col) pairs per warp in smem, padded to
// a multiple of 8 with (0, col=0) dummies so the inner loop is always an
// unroll-8 block: 8 independent LDG.128 (32 L2 sectors) in flight per warp.
// ---------------------------------------------------------------------------
__global__ void __launch_bounds__(32 * WARPS_PER_BLOCK)
spmm_kernel(const float* __restrict__ values,
            const float* __restrict__ w,
            const int*   __restrict__ cols32,
            float*       __restrict__ out) {
    const int warp = threadIdx.x >> 5;
    const int lane = threadIdx.x & 31;
    const int r    = blockIdx.x * WARPS_PER_BLOCK + warp;
    const int is64 = g_is64;

    __shared__ float2 stage[WARPS_PER_BLOCK][32];

    const int lo = g_row_start[r];
    const int hi = g_row_start[r + 1];

    float4 acc = make_float4(0.f, 0.f, 0.f, 0.f);
    const float4* __restrict__ w4 = (const float4*)w;   // w4[c*32 + lane]

    for (int base = lo; base < hi; base += 32) {
        const int m  = min(32, hi - base);
        const int mm = (m + 7) & ~7;                    // padded length (multiple of 8)

        // All lanes write: real pair if lane < m, else (0.0f, col 0) dummy.
        float v = 0.0f;
        int   c = 0;
        if (lane < m) {
            const int k = base + lane;
            v = values[k];
            c = is64 ? cols32[2 * k] : cols32[k];
        }
        stage[warp][lane] = make_float2(v, __int_as_float(c));
        __syncwarp();

        #pragma unroll 1
        for (int i = 0; i < mm; i += 8) {
            float2 p[8];
            float4 wv[8];
            #pragma unroll
            for (int j = 0; j < 8; j++) p[j] = stage[warp][i + j];
            #pragma unroll
            for (int j = 0; j < 8; j++)
                wv[j] = w4[(size_t)__float_as_int(p[j].y) * 32 + lane];
            #pragma unroll
            for (int j = 0; j < 8; j++) {
                acc.x = fmaf(p[j].x, wv[j].x, acc.x);
                acc.y = fmaf(p[j].x, wv[j].y, acc.y);
                acc.z = fmaf(p[j].x, wv[j].z, acc.z);
                acc.w = fmaf(p[j].x, wv[j].w, acc.w);
            }
        }
        __syncwarp();
    }

    ((float4*)out)[(size_t)r * 32 + lane] = acc;
}

// ---------------------------------------------------------------------------
// Launch
// Inputs (metadata order): values f32[NNZ], w f32[8192*128],
//                          rows int{32,64}[NNZ], cols int{32,64}[NNZ], n_rows
// ---------------------------------------------------------------------------
extern "C" void kernel_launch(void* const* d_in, const int* in_sizes, int n_in,
                              void* d_out, int out_size) {
    const float* values = (const float*)d_in[0];
    const float* w      = (const float*)d_in[1];
    const int*   rows32 = (const int*)d_in[2];
    const int*   cols32 = (const int*)d_in[3];
    float*       out    = (float*)d_out;

    const int nnz    = in_sizes[0];
    const int n_rows = out_size / OUT_UNITS;

    const int bs = 256;
    const int nthreads = (nnz + 3) / 4;
    build_offsets_kernel<<<(nthreads + bs - 1) / bs, bs>>>(rows32, nnz, n_rows);

    spmm_kernel<<<n_rows / WARPS_PER_BLOCK, 32 * WARPS_PER_BLOCK>>>(values, w, cols32, out);
}